// round 14
// baseline (speedup 1.0000x reference)
#include <cuda_runtime.h>
#include <cuda_fp16.h>
#include <cstdint>

// out[b,t,s] = dot(q[b,t,:], E_h[s - t/4 + 255]),  h = b % 8
//   E_h[j] = e1[h*256 + j]        j in [0,256)
//   E_h[j] = e2[h*256 + j - 255]  j in [256,511)
// B=128, T=1024, S=256, D=64.
//
// Per CTA: one b, TWO consecutive 128-row t-tiles (pipelined: tile-1 LDGs issue
// during tile-0 epilogue), 128 s-cols. Per tile: banded GEMM M=128 x N=160 x K=128,
// fp16 2-pass: D = q̂·Eh + q̂·El  (q̂=fp16(q), Eh=fp16(E), El=fp16(E-Eh)).
// out[t][s] = D[t][ s + 31 - t/4 ]: pre-shifted STS stage (wn-specialized
// predication), wm-split named barrier, LDS.128 + STG.128 readback.

#define T_DIM 1024
#define S_DIM 256
#define D_DIM 64

constexpr int BT = 128;
constexpr int NW = 160;
constexpr int RSTRIDE = 144;     // bytes per fp16 row: conflict-free LDSM
constexpr int SP2 = 132;         // fp32 stage stride (floats), 128 cols used

constexpr int SM_A  = 0;
constexpr int SM_BH = SM_A  + BT * RSTRIDE;      // 18432
constexpr int SM_BL = SM_BH + NW * RSTRIDE;      // 41472
constexpr int SM_IN_END = SM_BL + NW * RSTRIDE;  // 64512
constexpr int SM_TOTAL = BT * SP2 * 4;           // 67584 (stage aliases inputs)
static_assert(SM_TOTAL >= SM_IN_END, "stage must cover inputs");

__device__ __forceinline__ uint32_t smem_u32(const void* p) {
    uint32_t a;
    asm("{ .reg .u64 t; cvta.to.shared.u64 t, %1; cvt.u32.u64 %0, t; }"
        : "=r"(a) : "l"(p));
    return a;
}

#define LDSM_X4(r0, r1, r2, r3, addr)                                        \
    asm volatile("ldmatrix.sync.aligned.m8n8.x4.shared.b16 {%0,%1,%2,%3}, [%4];" \
                 : "=r"(r0), "=r"(r1), "=r"(r2), "=r"(r3) : "r"(addr))

#define LDSM_X2(r0, r1, addr)                                                \
    asm volatile("ldmatrix.sync.aligned.m8n8.x2.shared.b16 {%0,%1}, [%2];"   \
                 : "=r"(r0), "=r"(r1) : "r"(addr))

#define MMA16816(d, a, bb)                                                   \
    asm volatile("mma.sync.aligned.m16n8k16.row.col.f32.f16.f16.f32 "        \
                 "{%0,%1,%2,%3}, {%4,%5,%6,%7}, {%8,%9}, {%0,%1,%2,%3};"     \
                 : "+f"((d)[0]), "+f"((d)[1]), "+f"((d)[2]), "+f"((d)[3])    \
                 : "r"((a)[0]), "r"((a)[1]), "r"((a)[2]), "r"((a)[3]),       \
                   "r"((bb)[0]), "r"((bb)[1]))

__device__ __forceinline__ uint32_t h2bits(__half2 v) {
    return *reinterpret_cast<uint32_t*>(&v);
}

// fp16 split of 8 floats (two float4): hi = rn(fp16), lo = rn(fp16(residual))
__device__ __forceinline__ void split4h(float4 a, float4 b, uint4& hi, uint4& lo) {
    __half2 H0 = __floats2half2_rn(a.x, a.y);
    __half2 H1 = __floats2half2_rn(a.z, a.w);
    __half2 H2 = __floats2half2_rn(b.x, b.y);
    __half2 H3 = __floats2half2_rn(b.z, b.w);
    __half2 L0 = __floats2half2_rn(a.x - __low2float(H0), a.y - __high2float(H0));
    __half2 L1 = __floats2half2_rn(a.z - __low2float(H1), a.w - __high2float(H1));
    __half2 L2 = __floats2half2_rn(b.x - __low2float(H2), b.y - __high2float(H2));
    __half2 L3 = __floats2half2_rn(b.z - __low2float(H3), b.w - __high2float(H3));
    hi.x = h2bits(H0); hi.y = h2bits(H1); hi.z = h2bits(H2); hi.w = h2bits(H3);
    lo.x = h2bits(L0); lo.y = h2bits(L1); lo.z = h2bits(L2); lo.w = h2bits(L3);
}

// batch-issue all 18 LDG.128 for one tile (q: 8, E: 10)
#define LDG_TILE(T0, JMIN)                                                   \
    do {                                                                     \
        const float* qb_ = q + ((size_t)b * T_DIM + (T0)) * D_DIM;           \
        _Pragma("unroll")                                                    \
        for (int i = 0; i < 4; i++) {                                        \
            int idx = tid + 256 * i;                                         \
            const float* p = qb_ + (idx >> 3) * D_DIM + 8 * (idx & 7);       \
            vq[2 * i]     = *reinterpret_cast<const float4*>(p);             \
            vq[2 * i + 1] = *reinterpret_cast<const float4*>(p + 4);         \
        }                                                                    \
        _Pragma("unroll")                                                    \
        for (int i = 0; i < 5; i++) {                                        \
            int idx = tid + 256 * i;                                         \
            int r = idx >> 3;                                                \
            int j = (JMIN) + r;                                              \
            if (j > 510) j = 510;                                            \
            const float* src = (j < 256)                                     \
                ? (e1 + (size_t)(h * 256 + j) * D_DIM)                       \
                : (e2 + (size_t)(h * 256 + j - 255) * D_DIM);                \
            const float* p = src + 8 * (idx & 7);                            \
            ve[2 * i]     = *reinterpret_cast<const float4*>(p);             \
            ve[2 * i + 1] = *reinterpret_cast<const float4*>(p + 4);         \
        }                                                                    \
    } while (0)

__global__ void __launch_bounds__(256, 2)
srel_mma(const float* __restrict__ q,
         const float* __restrict__ e1,
         const float* __restrict__ e2,
         float* __restrict__ out)
{
    extern __shared__ char smem[];
    const uint32_t sb = smem_u32(smem);
    const int tid  = threadIdx.x;
    const int lane = tid & 31;
    const int wid  = tid >> 5;

    const int b  = blockIdx.z;
    const int h  = b & 7;
    const int sx = blockIdx.y;

    const int wm = wid & 1;
    const int wn = wid >> 1;
    const int g  = lane >> 2;
    const int tg = lane & 3;

    // LDSM / smem constants (tile-independent)
    const uint32_t aOff = (uint32_t)(wm * 64 + (lane & 15)) * RSTRIDE + (lane >> 4) * 16;
    const uint32_t bOff  = (uint32_t)(wn * 40 + (lane >> 4) * 8 + (lane & 7)) * RSTRIDE
                         + ((lane >> 3) & 1) * 16;
    const uint32_t bOff2 = (uint32_t)(wn * 40 + (lane & 7)) * RSTRIDE
                         + ((lane >> 3) & 1) * 16;
    const uint32_t a0  = sb + SM_A  + aOff;
    const uint32_t bH0 = sb + SM_BH + bOff;
    const uint32_t bH2 = sb + SM_BH + bOff2;
    const uint32_t bL0 = sb + SM_BL + bOff;
    const uint32_t bL2 = sb + SM_BL + bOff2;

    float4 vq[8];
    float4 ve[10];

    // prefetch tile 0
    {
        const int t00 = blockIdx.x * 2 * BT;
        const int jm0 = 128 * sx + 224 - (t00 >> 2);
        LDG_TILE(t00, jm0);
    }

    #pragma unroll
    for (int tt = 0; tt < 2; tt++) {
        const int t0 = (blockIdx.x * 2 + tt) * BT;

        // ---- convert + STS staged tiles from prefetched registers ----
        #pragma unroll
        for (int i = 0; i < 4; i++) {
            int idx = tid + 256 * i;
            int r = idx >> 3, mp = idx & 7;
            uint4 u;
            u.x = h2bits(__floats2half2_rn(vq[2*i].x, vq[2*i].y));
            u.y = h2bits(__floats2half2_rn(vq[2*i].z, vq[2*i].w));
            u.z = h2bits(__floats2half2_rn(vq[2*i+1].x, vq[2*i+1].y));
            u.w = h2bits(__floats2half2_rn(vq[2*i+1].z, vq[2*i+1].w));
            *reinterpret_cast<uint4*>(smem + SM_A + r * RSTRIDE + 16 * mp) = u;
        }
        #pragma unroll
        for (int i = 0; i < 5; i++) {
            int idx = tid + 256 * i;
            int r = idx >> 3, mp = idx & 7;
            uint4 hi, lo;
            split4h(ve[2*i], ve[2*i+1], hi, lo);
            *reinterpret_cast<uint4*>(smem + SM_BH + r * RSTRIDE + 16 * mp) = hi;
            *reinterpret_cast<uint4*>(smem + SM_BL + r * RSTRIDE + 16 * mp) = lo;
        }
        __syncthreads();

        // ---- MMA mainloop ----
        float acc[4][5][4] = {};
        #pragma unroll
        for (int kk = 0; kk < 4; kk++) {
            uint32_t a[4][4], bH[5][2], bL[5][2];
            #pragma unroll
            for (int mt = 0; mt < 4; mt++)
                LDSM_X4(a[mt][0], a[mt][1], a[mt][2], a[mt][3],
                        a0 + mt * 16 * RSTRIDE + kk * 32);
            #pragma unroll
            for (int p = 0; p < 2; p++)
                LDSM_X4(bH[2*p][0], bH[2*p][1], bH[2*p+1][0], bH[2*p+1][1],
                        bH0 + p * 16 * RSTRIDE + kk * 32);
            LDSM_X2(bH[4][0], bH[4][1], bH2 + 32 * RSTRIDE + kk * 32);
            #pragma unroll
            for (int p = 0; p < 2; p++)
                LDSM_X4(bL[2*p][0], bL[2*p][1], bL[2*p+1][0], bL[2*p+1][1],
                        bL0 + p * 16 * RSTRIDE + kk * 32);
            LDSM_X2(bL[4][0], bL[4][1], bL2 + 32 * RSTRIDE + kk * 32);
            #pragma unroll
            for (int mt = 0; mt < 4; mt++)
                #pragma unroll
                for (int nt = 0; nt < 5; nt++)
                    MMA16816(acc[mt][nt], a[mt], bH[nt]);
            #pragma unroll
            for (int mt = 0; mt < 4; mt++)
                #pragma unroll
                for (int nt = 0; nt < 5; nt++)
                    MMA16816(acc[mt][nt], a[mt], bL[nt]);
        }
        __syncthreads();   // inputs dead; stage aliases them

        // ---- accum -> stage, pre-shifted, wn-specialized predication ----
        // row r: stage col = n - off(r), off = 31 - r/4.
        // wn 1,2: c always in [0,128) -> unpredicated. wn 0: only c>=0 can fail.
        // wn 3: only c<128 can fail.
        float* st = reinterpret_cast<float*>(smem);
        #pragma unroll
        for (int mt = 0; mt < 4; mt++) {
            const int r0 = wm * 64 + mt * 16 + g;
            const int off0 = 31 - (r0 >> 2);
            const int off1 = off0 - 2;
            float* s0 = &st[r0 * SP2];
            float* s1 = &st[(r0 + 8) * SP2];
            if (wn == 0) {
                #pragma unroll
                for (int nt = 0; nt < 5; nt++) {
                    const int n = nt * 8 + 2 * tg;
                    int c0 = n - off0, c1 = n - off1;
                    if (c0 >= 0)  s0[c0]     = acc[mt][nt][0];
                    if (c0 >= -1) s0[c0 + 1] = acc[mt][nt][1];
                    if (c1 >= 0)  s1[c1]     = acc[mt][nt][2];
                    if (c1 >= -1) s1[c1 + 1] = acc[mt][nt][3];
                }
            } else if (wn == 3) {
                #pragma unroll
                for (int nt = 0; nt < 5; nt++) {
                    const int n = 120 + nt * 8 + 2 * tg;
                    int c0 = n - off0, c1 = n - off1;
                    if (c0 < 128) s0[c0]     = acc[mt][nt][0];
                    if (c0 < 127) s0[c0 + 1] = acc[mt][nt][1];
                    if (c1 < 128) s1[c1]     = acc[mt][nt][2];
                    if (c1 < 127) s1[c1 + 1] = acc[mt][nt][3];
                }
            } else {
                #pragma unroll
                for (int nt = 0; nt < 5; nt++) {
                    const int n = wn * 40 + nt * 8 + 2 * tg;
                    int c0 = n - off0, c1 = n - off1;
                    s0[c0]     = acc[mt][nt][0];
                    s0[c0 + 1] = acc[mt][nt][1];
                    s1[c1]     = acc[mt][nt][2];
                    s1[c1 + 1] = acc[mt][nt][3];
                }
            }
        }

        // ---- prefetch next tile's LDGs (acc regs are dead now) ----
        if (tt == 0) {
            const int t01 = blockIdx.x * 2 * BT + BT;
            const int jm1 = 128 * sx + 224 - (t01 >> 2);
            LDG_TILE(t01, jm1);
        }

        // wm-half barrier: rows [wm*64, wm*64+64) written only by wm-group
        asm volatile("bar.sync %0, 128;" :: "r"(1 + wm) : "memory");

        // ---- aligned LDS.128 readback + coalesced STG.128, wm-local rows ----
        float* ob = out + ((size_t)b * T_DIM + t0) * S_DIM + 128 * sx;
        const int lw = wid >> 1;     // warp index within wm-group (0..3)
        #pragma unroll
        for (int i = 0; i < 16; i++) {
            int row = wm * 64 + i * 4 + lw;
            float4 v = *reinterpret_cast<const float4*>(&st[row * SP2 + 4 * lane]);
            *reinterpret_cast<float4*>(ob + row * S_DIM + 4 * lane) = v;
        }

        if (tt == 0) __syncthreads();   // stage fully read before next STS
    }
}

extern "C" void kernel_launch(void* const* d_in, const int* in_sizes, int n_in,
                              void* d_out, int out_size)
{
    const float* q  = (const float*)d_in[0];
    const float* e1 = (const float*)d_in[1];
    const float* e2 = (const float*)d_in[2];
    float* out = (float*)d_out;

    cudaFuncSetAttribute(srel_mma,
                         cudaFuncAttributeMaxDynamicSharedMemorySize, SM_TOTAL);
    dim3 grid(T_DIM / (2 * BT), S_DIM / 128, 128);   // (4, 2, 128) = 1024 blocks
    srel_mma<<<grid, 256, SM_TOTAL>>>(q, e1, e2, out);
}